// round 2
// baseline (speedup 1.0000x reference)
#include <cuda_runtime.h>
#include <cuda_bf16.h>

#define BB 32
#define CC 32
#define HH 480
#define WW 480
#define LL 120
#define HALF 60
#define PLANE (HH*WW)
#define RBLK 30          // reduce blocks per batch
#define PITCH 124        // smem tile pitch (floats)

// per-(batch, reduce-block) partials: [cnt, sum_y, sum_x] — written every
// replay before being read, so no zero-init kernel and no atomics needed.
__device__ float g_part[BB * RBLK * 3];
// per-batch crop window: {y_start, ry, x_start, rx}
__device__ int4 g_pos[BB];

// ---------------------------------------------------------------------------
// Kernel 1: per-batch masked centroid partial reduction over channel-1 plane.
// Grid (RBLK, BB), block 256. float4 loads (plane offset is 16B aligned).
// ---------------------------------------------------------------------------
__global__ void reduce_pos_kernel(const float* __restrict__ in) {
    const int b = blockIdx.y;
    const float4* __restrict__ plane =
        (const float4*)(in + (size_t)b * CC * PLANE + (size_t)PLANE);
    const int n4 = PLANE / 4;   // 57600; a float4 never crosses a row (480%4==0)

    float cnt = 0.0f, sy = 0.0f, sx = 0.0f;
    const int stride = gridDim.x * blockDim.x;
    for (int i = blockIdx.x * blockDim.x + threadIdx.x; i < n4; i += stride) {
        float4 v = plane[i];
        int idx = i * 4;
        int yi  = idx / WW;
        float y  = (float)yi;
        float xb = (float)(idx - yi * WW);
        if (v.x == 1.0f) { cnt += 1.0f; sy += y; sx += xb;        }
        if (v.y == 1.0f) { cnt += 1.0f; sy += y; sx += xb + 1.0f; }
        if (v.z == 1.0f) { cnt += 1.0f; sy += y; sx += xb + 2.0f; }
        if (v.w == 1.0f) { cnt += 1.0f; sy += y; sx += xb + 3.0f; }
    }
    #pragma unroll
    for (int o = 16; o > 0; o >>= 1) {
        cnt += __shfl_down_sync(0xffffffffu, cnt, o);
        sy  += __shfl_down_sync(0xffffffffu, sy,  o);
        sx  += __shfl_down_sync(0xffffffffu, sx,  o);
    }
    __shared__ float s[3][8];
    const int lane = threadIdx.x & 31;
    const int w    = threadIdx.x >> 5;
    if (lane == 0) { s[0][w] = cnt; s[1][w] = sy; s[2][w] = sx; }
    __syncthreads();
    if (threadIdx.x == 0) {
        float c = 0.0f, a = 0.0f, d = 0.0f;
        #pragma unroll
        for (int i = 0; i < 8; i++) { c += s[0][i]; a += s[1][i]; d += s[2][i]; }
        float* p = &g_part[(b * RBLK + blockIdx.x) * 3];
        p[0] = c; p[1] = a; p[2] = d;
    }
}

// ---------------------------------------------------------------------------
// Kernel 2: finalize positions. 1 block, 1024 threads: warp b handles batch b.
// ---------------------------------------------------------------------------
__global__ void finalize_kernel() {
    const int b    = threadIdx.x >> 5;
    const int lane = threadIdx.x & 31;
    float cnt = 0.0f, sy = 0.0f, sx = 0.0f;
    if (lane < RBLK) {
        const float* p = &g_part[(b * RBLK + lane) * 3];
        cnt = p[0]; sy = p[1]; sx = p[2];
    }
    #pragma unroll
    for (int o = 16; o > 0; o >>= 1) {
        cnt += __shfl_down_sync(0xffffffffu, cnt, o);
        sy  += __shfl_down_sync(0xffffffffu, sy,  o);
        sx  += __shfl_down_sync(0xffffffffu, sx,  o);
    }
    if (lane == 0) {
        float denom = fmaxf(cnt, 1.0f);
        // rintf = round-half-even, matching jnp.round
        int py = (cnt > 0.0f) ? (int)rintf(sy / denom) : (HH / 2);
        int px = (cnt > 0.0f) ? (int)rintf(sx / denom) : (WW / 2);
        int ys = max(py - HALF, 0);
        int ye = min(py + HALF, HH);
        int xs = max(px - HALF, 0);
        int xe = min(px + HALF, WW);
        g_pos[b] = make_int4(ys, ye - ys, xs, xe - xs);
    }
}

// ---------------------------------------------------------------------------
// Kernel 3: crop + bilinear resize. Grid (CC, BB): one block per (b,c) tile.
// Stages the (ry+1)x(rx+1) source crop into smem with edge replication so the
// inner loop needs no clamping, then computes 120x120 outputs, 4-wide float4
// stores. Global traffic: each source float read exactly once.
// ---------------------------------------------------------------------------
extern __shared__ float tile[];

__global__ void __launch_bounds__(256) crop_resize_kernel(
        const float* __restrict__ in, float* __restrict__ out) {
    const int c = blockIdx.x;
    const int b = blockIdx.y;

    __shared__ int4 sp;
    if (threadIdx.x == 0) sp = g_pos[b];
    __syncthreads();
    const int ys = sp.x, ry = sp.y, xs = sp.z, rx = sp.w;

    const float* __restrict__ img = in + (size_t)(b * CC + c) * PLANE;

    // stage (ry+1) rows x (rx+1) cols, replicating last row/col
    {
        const int lane = threadIdx.x & 31;
        const int w    = threadIdx.x >> 5;
        for (int r = w; r <= ry; r += 8) {
            const float* __restrict__ src = img + (ys + min(r, ry - 1)) * WW + xs;
            float* dst = tile + r * PITCH;
            for (int cc = lane; cc <= rx; cc += 32)
                dst[cc] = src[min(cc, rx - 1)];
        }
    }
    __syncthreads();

    const float fy = (float)ry / (float)LL;
    const float fx = (float)rx / (float)LL;
    float* __restrict__ obase = out + (size_t)(b * CC + c) * (LL * LL);

    // 3600 work items: (oy, group of 4 x)
    for (int wrk = threadIdx.x; wrk < LL * (LL / 4); wrk += 256) {
        int oy = wrk / (LL / 4);
        int ox = (wrk - oy * (LL / 4)) * 4;

        float syv = fmaxf(((float)oy + 0.5f) * fy - 0.5f, 0.0f);
        int   y0  = (int)syv;
        float wy  = syv - (float)y0;
        const float* __restrict__ r0 = tile + y0 * PITCH;
        const float* __restrict__ r1 = r0 + PITCH;

        float4 res;
        float* rp = (float*)&res;
        #pragma unroll
        for (int j = 0; j < 4; j++) {
            float sxv = fmaxf(((float)(ox + j) + 0.5f) * fx - 0.5f, 0.0f);
            int   x0  = (int)sxv;
            float wx  = sxv - (float)x0;
            float v00 = r0[x0], v01 = r0[x0 + 1];
            float v10 = r1[x0], v11 = r1[x0 + 1];
            float top = v00 * (1.0f - wx) + v01 * wx;
            float bot = v10 * (1.0f - wx) + v11 * wx;
            rp[j] = top * (1.0f - wy) + bot * wy;
        }
        *(float4*)(obase + oy * LL + ox) = res;
    }
}

extern "C" void kernel_launch(void* const* d_in, const int* in_sizes, int n_in,
                              void* d_out, int out_size) {
    const float* in = (const float*)d_in[0];
    float* out = (float*)d_out;

    static bool attr_set = false;
    if (!attr_set) {
        cudaFuncSetAttribute(crop_resize_kernel,
                             cudaFuncAttributeMaxDynamicSharedMemorySize,
                             (LL + 1) * PITCH * 4);
        attr_set = true;
    }

    reduce_pos_kernel<<<dim3(RBLK, BB), 256>>>(in);
    finalize_kernel<<<1, 1024>>>();
    crop_resize_kernel<<<dim3(CC, BB), 256, (LL + 1) * PITCH * 4>>>(in, out);
}

// round 3
// speedup vs baseline: 2.2632x; 2.2632x over previous
#include <cuda_runtime.h>
#include <cuda_bf16.h>

#define BB 32
#define CC 32
#define HH 480
#define WW 480
#define LL 120
#define HALF 60
#define PLANE (HH*WW)
#define RB 60            // reduce blocks per batch (8 rows each)

// per-(batch, reduce-block) partials: [cnt, sum_y, sum_x].
// Fully rewritten every replay before being read -> no zero-init, no atomics.
__device__ float g_part[BB * RB * 3];

// ---------------------------------------------------------------------------
// Kernel 1: masked centroid partials over channel-1 plane.
// Grid (RB, BB), block 256 (8 warps). Warp w owns row blockIdx.x*8 + w.
// Channel 1 is exactly {0.0, 1.0}, so mask == value: branch-free FMA stream.
// ---------------------------------------------------------------------------
__global__ void __launch_bounds__(256) reduce_pos_kernel(const float* __restrict__ in) {
    const int b    = blockIdx.y;
    const int w    = threadIdx.x >> 5;
    const int lane = threadIdx.x & 31;
    const int y    = blockIdx.x * 8 + w;

    const float4* __restrict__ row =
        (const float4*)(in + (size_t)b * CC * PLANE + (size_t)PLANE + (size_t)y * WW);

    float c = 0.0f, sx = 0.0f;
    #pragma unroll
    for (int k = 0; k < 4; k++) {
        const int xi = lane + 32 * k;          // float4 index in row, 120 per row
        if (xi < WW / 4) {
            float4 v  = row[xi];
            float  s4 = (v.x + v.y) + (v.z + v.w);
            c  += s4;
            sx += (float)(4 * xi) * s4 + (v.y + 2.0f * v.z + 3.0f * v.w);
        }
    }
    float sy = (float)y * c;                   // row constant per warp

    #pragma unroll
    for (int o = 16; o > 0; o >>= 1) {
        c  += __shfl_down_sync(0xffffffffu, c,  o);
        sy += __shfl_down_sync(0xffffffffu, sy, o);
        sx += __shfl_down_sync(0xffffffffu, sx, o);
    }
    __shared__ float s[3][8];
    if (lane == 0) { s[0][w] = c; s[1][w] = sy; s[2][w] = sx; }
    __syncthreads();
    if (threadIdx.x == 0) {
        float cc = 0.0f, ay = 0.0f, ax = 0.0f;
        #pragma unroll
        for (int i = 0; i < 8; i++) { cc += s[0][i]; ay += s[1][i]; ax += s[2][i]; }
        float* p = &g_part[(b * RB + blockIdx.x) * 3];
        p[0] = cc; p[1] = ay; p[2] = ax;
    }
}

// ---------------------------------------------------------------------------
// Kernel 2: crop + bilinear resize, channel-batched gather (no smem tile).
// Grid (LL/4, CC/4, BB), block (128, 4).
// Thread = one (oy, ox) pixel; loops over 4 channels reusing the weights and
// keeping 16 independent LDG in flight. Warp 0 of each block redundantly
// finalizes the crop window from the 60 partials (L2-resident, ~90 loads).
// ---------------------------------------------------------------------------
__global__ void __launch_bounds__(512) crop_resize_kernel(
        const float* __restrict__ in, float* __restrict__ out) {
    const int b  = blockIdx.z;
    const int c0 = blockIdx.y * 4;

    __shared__ int   swin[4];    // ys, ry, xs, rx
    __shared__ float sfac[2];    // fy, fx

    if (threadIdx.y == 0 && threadIdx.x < 32) {
        const int lane = threadIdx.x;
        float c = 0.0f, sy = 0.0f, sx = 0.0f;
        if (lane < RB / 2) {
            const float* p = &g_part[(b * RB + lane) * 3];
            const float* q = &g_part[(b * RB + lane + RB / 2) * 3];
            c  = p[0] + q[0];
            sy = p[1] + q[1];
            sx = p[2] + q[2];
        }
        #pragma unroll
        for (int o = 16; o > 0; o >>= 1) {
            c  += __shfl_down_sync(0xffffffffu, c,  o);
            sy += __shfl_down_sync(0xffffffffu, sy, o);
            sx += __shfl_down_sync(0xffffffffu, sx, o);
        }
        if (lane == 0) {
            float denom = fmaxf(c, 1.0f);
            // rintf = round-half-even, matching jnp.round
            int py = (c > 0.0f) ? (int)rintf(sy / denom) : (HH / 2);
            int px = (c > 0.0f) ? (int)rintf(sx / denom) : (WW / 2);
            int ys = max(py - HALF, 0);
            int ry = min(py + HALF, HH) - ys;
            int xs = max(px - HALF, 0);
            int rx = min(px + HALF, WW) - xs;
            swin[0] = ys; swin[1] = ry; swin[2] = xs; swin[3] = rx;
            sfac[0] = (float)ry / (float)LL;
            sfac[1] = (float)rx / (float)LL;
        }
    }
    __syncthreads();

    const int ox = threadIdx.x;
    if (ox >= LL) return;
    const int oy = blockIdx.x * 4 + threadIdx.y;

    const int   ys = swin[0], ry = swin[1], xs = swin[2], rx = swin[3];
    const float fy = sfac[0], fx = sfac[1];

    float syv = fmaxf(((float)oy + 0.5f) * fy - 0.5f, 0.0f);
    float sxv = fmaxf(((float)ox + 0.5f) * fx - 0.5f, 0.0f);
    int y0 = (int)syv;                  // >= 0 -> trunc == floor
    int x0 = (int)sxv;
    int y1 = min(y0 + 1, ry - 1);
    int x1 = min(x0 + 1, rx - 1);
    float wy = syv - (float)y0;
    float wx = sxv - (float)x0;

    const int o00 = (ys + y0) * WW + xs + x0;
    const int o01 = (ys + y0) * WW + xs + x1;
    const int o10 = (ys + y1) * WW + xs + x0;
    const int o11 = (ys + y1) * WW + xs + x1;

    const float* __restrict__ img =
        in + ((size_t)b * CC + c0) * PLANE;
    float* __restrict__ obase =
        out + (((size_t)(b * CC + c0)) * LL + oy) * LL + ox;

    float v00[4], v01[4], v10[4], v11[4];
    #pragma unroll
    for (int c = 0; c < 4; c++) {
        const float* __restrict__ p = img + (size_t)c * PLANE;
        v00[c] = p[o00];
        v01[c] = p[o01];
        v10[c] = p[o10];
        v11[c] = p[o11];
    }
    #pragma unroll
    for (int c = 0; c < 4; c++) {
        float top = v00[c] * (1.0f - wx) + v01[c] * wx;
        float bot = v10[c] * (1.0f - wx) + v11[c] * wx;
        float res = top * (1.0f - wy) + bot * wy;
        obase[(size_t)c * (LL * LL)] = res;
    }
}

extern "C" void kernel_launch(void* const* d_in, const int* in_sizes, int n_in,
                              void* d_out, int out_size) {
    const float* in = (const float*)d_in[0];
    float* out = (float*)d_out;

    reduce_pos_kernel<<<dim3(RB, BB), 256>>>(in);

    dim3 cb(128, 4);                    // 512 threads
    dim3 cg(LL / 4, CC / 4, BB);        // 30 x 8 x 32 = 7680 blocks
    crop_resize_kernel<<<cg, cb>>>(in, out);
}